// round 1
// baseline (speedup 1.0000x reference)
#include <cuda_runtime.h>
#include <math.h>

// Problem dims
#define BATCH 8
#define SEQ   2048
#define DIM   1024
#define HEAD  64
#define MROWS (BATCH * SEQ)   // 16384

// Attention tiling
#define BQ  32                // queries per q-tile
#define TK  64                // keys per k-tile
#define NQT (SEQ / BQ)        // 64 q-tiles per batch

#define NEG_BIG (-3.0e38f)

// Scratch for Q, K, V projections (device globals: no allocation allowed)
__device__ float g_Q[MROWS * HEAD];
__device__ float g_K[MROWS * HEAD];
__device__ float g_V[MROWS * HEAD];

// ---------------------------------------------------------------------------
// Kernel 1: QKV projection.  C[16384,64] = x[16384,1024] @ W[1024,64]
// Block: 256 threads, tile 64 rows x 64 cols, per-thread 4x4 micro-tile.
// gridDim = (MROWS/64, 3); blockIdx.y selects which W / destination.
// ---------------------------------------------------------------------------
__global__ __launch_bounds__(256, 4)
void proj_kernel(const float* __restrict__ x,
                 const float* __restrict__ Wk,
                 const float* __restrict__ Wq,
                 const float* __restrict__ Wv)
{
    __shared__ float Xs[64][36];   // [row][k]  (row padded 32->36, float4 aligned)
    __shared__ float Ws[32][64];   // [k][col]

    const int tid  = threadIdx.x;
    const int tx   = tid & 15;     // col group 0..15 (cols tx*4 .. tx*4+3)
    const int ty   = tid >> 4;     // row group 0..15 (rows ty*4 .. ty*4+3)
    const int row0 = blockIdx.x * 64;

    const float* W;
    float* out;
    if (blockIdx.y == 0)      { W = Wq; out = g_Q; }
    else if (blockIdx.y == 1) { W = Wk; out = g_K; }
    else                      { W = Wv; out = g_V; }

    float acc[4][4];
    #pragma unroll
    for (int i = 0; i < 4; i++)
        #pragma unroll
        for (int j = 0; j < 4; j++) acc[i][j] = 0.0f;

    for (int k0 = 0; k0 < DIM; k0 += 32) {
        // load X tile: 64 rows x 32 k  (coalesced float4)
        {
            const int r   = tid >> 3;   // 0..31
            const int seg = tid & 7;    // 0..7 -> k offset seg*4
            float4 v0 = *(const float4*)&x[(size_t)(row0 + r)      * DIM + k0 + seg * 4];
            float4 v1 = *(const float4*)&x[(size_t)(row0 + r + 32) * DIM + k0 + seg * 4];
            *(float4*)&Xs[r][seg * 4]      = v0;
            *(float4*)&Xs[r + 32][seg * 4] = v1;
        }
        // load W tile: 32 k x 64 cols
        {
            const int kk  = tid >> 4;   // 0..15
            const int seg = tid & 15;   // 0..15 -> col seg*4
            *(float4*)&Ws[kk][seg * 4]      = *(const float4*)&W[(size_t)(k0 + kk)      * HEAD + seg * 4];
            *(float4*)&Ws[kk + 16][seg * 4] = *(const float4*)&W[(size_t)(k0 + kk + 16) * HEAD + seg * 4];
        }
        __syncthreads();

        #pragma unroll
        for (int kk = 0; kk < 32; kk++) {
            float4 b4 = *(const float4*)&Ws[kk][tx * 4];
            float bb[4] = { b4.x, b4.y, b4.z, b4.w };
            float aa[4];
            #pragma unroll
            for (int i = 0; i < 4; i++) aa[i] = Xs[ty * 4 + i][kk];
            #pragma unroll
            for (int i = 0; i < 4; i++)
                #pragma unroll
                for (int j = 0; j < 4; j++)
                    acc[i][j] += aa[i] * bb[j];
        }
        __syncthreads();
    }

    #pragma unroll
    for (int i = 0; i < 4; i++) {
        float4 o;
        o.x = acc[i][0]; o.y = acc[i][1]; o.z = acc[i][2]; o.w = acc[i][3];
        *(float4*)&out[(size_t)(row0 + ty * 4 + i) * HEAD + tx * 4] = o;
    }
}

// ---------------------------------------------------------------------------
// Kernel 2: fused causal flash attention (fp32).
// Block: 128 threads = 32 queries x 4 "parts".  Each block handles the q-tile
// pair (i, NQT-1-i) -> uniform 33 key-tiles of work per block.
//
// Per k-tile:
//   scores : each part owns 16 keys (rotated index for bank-conflict-free LDS)
//   softmax: common row max via shfl across the 4 parts; per-part partial l
//   PV     : p exchanged through smem; each part owns 16 of the 64 h dims,
//            accumulating over ALL 64 keys -> no final O combine needed.
// ---------------------------------------------------------------------------
__global__ __launch_bounds__(128, 4)
void attn_kernel(float* __restrict__ zout)
{
    __shared__ float Ks[TK][HEAD + 4];   // [key][d], row 68 floats
    __shared__ float Vs[TK][HEAD + 4];   // [key][h]
    __shared__ float Ps[TK][BQ];         // [key][q]

    const int tid  = threadIdx.x;
    const int q    = tid >> 2;    // 0..31 local query
    const int part = tid & 3;     // 0..3
    const int b    = blockIdx.y;
    const size_t base = (size_t)b * SEQ * HEAD;

    #pragma unroll 1
    for (int pass = 0; pass < 2; pass++) {
        const int qt = (pass == 0) ? (int)blockIdx.x : (NQT - 1 - (int)blockIdx.x);
        const int qg = qt * BQ + q;          // query index within batch

        // Q row into registers, pre-scaled by 1/sqrt(64)
        float4 Q4[16];
        #pragma unroll
        for (int d4 = 0; d4 < 16; d4++) {
            float4 v = *(const float4*)&g_Q[base + (size_t)qg * HEAD + d4 * 4];
            v.x *= 0.125f; v.y *= 0.125f; v.z *= 0.125f; v.w *= 0.125f;
            Q4[d4] = v;
        }

        float O[16];
        #pragma unroll
        for (int i = 0; i < 16; i++) O[i] = 0.0f;
        float m_run = NEG_BIG;
        float l_run = 0.0f;

        const int nkt = qt / 2 + 1;          // # of 64-key tiles (covers keys <= max qg)

        #pragma unroll 1
        for (int kt = 0; kt < nkt; kt++) {
            const int k0 = kt * TK;
            __syncthreads();   // protect Ks/Vs/Ps from previous iteration readers

            // load K and V tiles (64 keys x 64 dims each), coalesced
            for (int idx = tid; idx < TK * 16; idx += 128) {
                const int key = idx >> 4;
                const int d4  = idx & 15;
                *(float4*)&Ks[key][d4 * 4] = *(const float4*)&g_K[base + (size_t)(k0 + key) * HEAD + d4 * 4];
                *(float4*)&Vs[key][d4 * 4] = *(const float4*)&g_V[base + (size_t)(k0 + key) * HEAD + d4 * 4];
            }
            __syncthreads();

            // ---- scores: 16 keys per part, rotated local index ----
            const bool lastTile = (kt == nkt - 1);
            float sv[16];
            #pragma unroll
            for (int jj = 0; jj < 16; jj++) {
                const int jloc = part * 16 + ((jj + 2 * part) & 15);
                float s0 = 0.f, s1 = 0.f, s2 = 0.f, s3 = 0.f;
                #pragma unroll
                for (int d4 = 0; d4 < 16; d4++) {
                    float4 K4 = *(const float4*)&Ks[jloc][d4 * 4];
                    s0 += Q4[d4].x * K4.x;
                    s1 += Q4[d4].y * K4.y;
                    s2 += Q4[d4].z * K4.z;
                    s3 += Q4[d4].w * K4.w;
                }
                float s = (s0 + s1) + (s2 + s3);
                if (lastTile && (k0 + jloc > qg)) s = NEG_BIG;   // causal mask
                sv[jj] = s;
            }

            // ---- online softmax with common row max across the 4 parts ----
            float smax = sv[0];
            #pragma unroll
            for (int jj = 1; jj < 16; jj++) smax = fmaxf(smax, sv[jj]);
            smax = fmaxf(smax, __shfl_xor_sync(0xffffffffu, smax, 1));
            smax = fmaxf(smax, __shfl_xor_sync(0xffffffffu, smax, 2));

            const float m_new = fmaxf(m_run, smax);
            const float alpha = __expf(m_run - m_new);  // 0 on first tile

            float p[16];
            float psum = 0.0f;
            #pragma unroll
            for (int jj = 0; jj < 16; jj++) {
                p[jj] = __expf(sv[jj] - m_new);          // masked -> exp(-huge) = 0
                psum += p[jj];
            }
            l_run = l_run * alpha + psum;
            m_run = m_new;
            #pragma unroll
            for (int i = 0; i < 16; i++) O[i] *= alpha;

            // publish p for all parts
            #pragma unroll
            for (int jj = 0; jj < 16; jj++) {
                const int jloc = part * 16 + ((jj + 2 * part) & 15);
                Ps[jloc][q] = p[jj];
            }
            __syncthreads();

            // ---- PV: all 64 keys, this part's 16 h dims (rotated chunks) ----
            #pragma unroll 4
            for (int j = 0; j < TK; j++) {
                const float pj = Ps[j][q];
                #pragma unroll
                for (int u = 0; u < 4; u++) {
                    const int col = part * 16 + 4 * ((u + part) & 3);
                    float4 V4 = *(const float4*)&Vs[j][col];
                    O[u * 4 + 0] += pj * V4.x;
                    O[u * 4 + 1] += pj * V4.y;
                    O[u * 4 + 2] += pj * V4.z;
                    O[u * 4 + 3] += pj * V4.w;
                }
            }
        }

        // total l across the 4 parts (same m sequence -> directly summable)
        float l_tot = l_run;
        l_tot += __shfl_xor_sync(0xffffffffu, l_tot, 1);
        l_tot += __shfl_xor_sync(0xffffffffu, l_tot, 2);
        const float inv = 1.0f / l_tot;

        #pragma unroll
        for (int u = 0; u < 4; u++) {
            const int col = part * 16 + 4 * ((u + part) & 3);
            float4 o;
            o.x = O[u * 4 + 0] * inv;
            o.y = O[u * 4 + 1] * inv;
            o.z = O[u * 4 + 2] * inv;
            o.w = O[u * 4 + 3] * inv;
            *(float4*)&zout[base + (size_t)qg * HEAD + col] = o;
        }
    }
}

// ---------------------------------------------------------------------------
// kernel_launch
// inputs (metadata order): x, Wk, Wq, Wv ; output z [8,2048,64] fp32
// ---------------------------------------------------------------------------
extern "C" void kernel_launch(void* const* d_in, const int* in_sizes, int n_in,
                              void* d_out, int out_size)
{
    const float* x  = (const float*)d_in[0];
    const float* Wk = (const float*)d_in[1];
    const float* Wq = (const float*)d_in[2];
    const float* Wv = (const float*)d_in[3];
    float* z = (float*)d_out;
    (void)in_sizes; (void)n_in; (void)out_size;

    dim3 pgrid(MROWS / 64, 3);
    proj_kernel<<<pgrid, 256>>>(x, Wk, Wq, Wv);

    dim3 agrid(NQT / 2, BATCH);
    attn_kernel<<<agrid, 128>>>(z);
}

// round 4
// speedup vs baseline: 1.4090x; 1.4090x over previous
#include <cuda_runtime.h>
#include <math.h>

#define BATCH 8
#define SEQ   2048
#define DIM   1024
#define HEAD  64
#define MROWS (BATCH * SEQ)      // 16384
#define BQ  32
#define TK  64
#define NQT (SEQ / BQ)           // 64
#define NEG_BIG (-3.0e38f)

// Scratch for Q, K, V projections (no allocation allowed -> device globals)
__device__ float g_Q[MROWS * HEAD];
__device__ float g_K[MROWS * HEAD];
__device__ float g_V[MROWS * HEAD];

// ---------------- packed f32x2 helpers (Blackwell FFMA2) ----------------
#define FMA2(d, a, b, c) \
    asm("fma.rn.f32x2 %0, %1, %2, %3;" : "=l"(d) : "l"(a), "l"(b), "l"(c))

__device__ __forceinline__ unsigned long long pack2(float x) {
    unsigned long long r;
    unsigned u = __float_as_uint(x);
    asm("mov.b64 %0, {%1, %1};" : "=l"(r) : "r"(u));
    return r;
}
__device__ __forceinline__ float2 unpack2(unsigned long long v) {
    unsigned a, b;
    asm("mov.b64 {%0, %1}, %2;" : "=r"(a), "=r"(b) : "l"(v));
    return make_float2(__uint_as_float(a), __uint_as_float(b));
}

// ---------------------------------------------------------------------------
// Kernel 1: QKV projection with FFMA2.  C[16384,64] = x[16384,1024] @ W[1024,64]
// 128 threads, tile 128 rows x 64 cols, per-thread 8x8 micro-tile.
// ---------------------------------------------------------------------------
__global__ __launch_bounds__(128, 4)
void proj_kernel(const float* __restrict__ x,
                 const float* __restrict__ Wk,
                 const float* __restrict__ Wq,
                 const float* __restrict__ Wv)
{
    __shared__ float Xs[128][36];   // [row][k], cols 0..31 used of 36
    __shared__ float Ws[32][68];    // [k][col]

    const int tid  = threadIdx.x;
    const int tx   = tid & 7;       // col group: cols tx*8 .. tx*8+7
    const int ty   = tid >> 3;      // row set: rows ty + 16*i
    const int row0 = blockIdx.x * 128;

    const float* W;
    float* out;
    if (blockIdx.y == 0)      { W = Wq; out = g_Q; }
    else if (blockIdx.y == 1) { W = Wk; out = g_K; }
    else                      { W = Wv; out = g_V; }

    unsigned long long acc2[8][4];
    #pragma unroll
    for (int i = 0; i < 8; i++)
        #pragma unroll
        for (int p = 0; p < 4; p++) acc2[i][p] = 0ULL;

    for (int k0 = 0; k0 < DIM; k0 += 32) {
        #pragma unroll
        for (int it = 0; it < 8; it++) {
            const int idx = tid + it * 128;
            const int r   = idx >> 3;
            const int seg = idx & 7;
            *(float4*)&Xs[r][seg * 4] =
                *(const float4*)&x[(size_t)(row0 + r) * DIM + k0 + seg * 4];
        }
        #pragma unroll
        for (int it = 0; it < 4; it++) {
            const int idx = tid + it * 128;
            const int kk  = idx >> 4;
            const int seg = idx & 15;
            *(float4*)&Ws[kk][seg * 4] =
                *(const float4*)&W[(size_t)(k0 + kk) * HEAD + seg * 4];
        }
        __syncthreads();

        #pragma unroll 16
        for (int kk = 0; kk < 32; kk++) {
            unsigned long long b[4];
            #pragma unroll
            for (int p = 0; p < 4; p++)
                b[p] = *(const unsigned long long*)&Ws[kk][tx * 8 + 2 * p];
            #pragma unroll
            for (int i = 0; i < 8; i++) {
                unsigned long long aa = pack2(Xs[ty + 16 * i][kk]);
                #pragma unroll
                for (int p = 0; p < 4; p++)
                    FMA2(acc2[i][p], aa, b[p], acc2[i][p]);
            }
        }
        __syncthreads();
    }

    #pragma unroll
    for (int i = 0; i < 8; i++) {
        float2 f0 = unpack2(acc2[i][0]);
        float2 f1 = unpack2(acc2[i][1]);
        float2 f2 = unpack2(acc2[i][2]);
        float2 f3 = unpack2(acc2[i][3]);
        const size_t rb = (size_t)(row0 + ty + 16 * i) * HEAD + tx * 8;
        float4 o1; o1.x = f0.x; o1.y = f0.y; o1.z = f1.x; o1.w = f1.y;
        float4 o2; o2.x = f2.x; o2.y = f2.y; o2.z = f3.x; o2.w = f3.y;
        *(float4*)&out[rb]     = o1;
        *(float4*)&out[rb + 4] = o2;
    }
}

// ---------------------------------------------------------------------------
// Kernel 2: fused causal flash attention, GEMM-style register tiling.
// 128 threads = 8 (ty, 4 queries) x 16 (tx).  One 32-query tile per block,
// heavy-first (qt = 63 - bx).  Single shared K/V buffer: K loaded swizzled
// for the score phase; V fetched to registers during scores, written to the
// same buffer for the PV phase.
// ---------------------------------------------------------------------------
__global__ __launch_bounds__(128, 4)
void attn_kernel(float* __restrict__ zout)
{
    __shared__ float Qs[BQ][64];    // [q][d]   (FULL 64-wide rows — R2 bugfix)
    __shared__ float KV[TK][64];    // K phase: [key][4*(d4^(key&15))+c]; V phase: [key][h]
    __shared__ float Ps[TK][36];    // [key][q]

    const int tid = threadIdx.x;
    const int tx  = tid & 15;
    const int ty  = tid >> 4;
    const int q0  = ty * 4;
    const int qt  = (NQT - 1) - blockIdx.x;
    const int b   = blockIdx.y;
    const size_t base = (size_t)b * SEQ * HEAD;
    const int qg0 = qt * BQ;

    // Q tile -> smem, pre-scaled by 1/sqrt(64)
    #pragma unroll
    for (int it = 0; it < 4; it++) {
        const int idx = tid + it * 128;
        const int r   = idx >> 4;
        const int d4  = idx & 15;
        float4 v = *(const float4*)&g_Q[base + (size_t)(qg0 + r) * HEAD + d4 * 4];
        v.x *= 0.125f; v.y *= 0.125f; v.z *= 0.125f; v.w *= 0.125f;
        *(float4*)&Qs[r][d4 * 4] = v;
    }

    float O[4][4];
    float m_run[4], l_run[4];
    #pragma unroll
    for (int i = 0; i < 4; i++) {
        m_run[i] = NEG_BIG; l_run[i] = 0.0f;
        #pragma unroll
        for (int c = 0; c < 4; c++) O[i][c] = 0.0f;
    }

    const int nkt = qt / 2 + 1;

    #pragma unroll 1
    for (int kt = 0; kt < nkt; kt++) {
        const int k0 = kt * TK;
        __syncthreads();   // sync_a: prev PV done reading KV/Ps (and Qs visible, kt=0)

        // load K (swizzled) into KV; issue V loads into registers (hidden by scores)
        float4 vreg[8];
        #pragma unroll
        for (int it = 0; it < 8; it++) {
            const int idx = tid + it * 128;
            const int key = idx >> 4;
            const int d4  = idx & 15;
            *(float4*)&KV[key][4 * (d4 ^ (key & 15))] =
                *(const float4*)&g_K[base + (size_t)(k0 + key) * HEAD + d4 * 4];
            vreg[it] = *(const float4*)&g_V[base + (size_t)(k0 + key) * HEAD + d4 * 4];
        }
        __syncthreads();   // sync_b: K tile ready

        // ---- scores: acc[4 q][4 k], keys j*16 + tx ----
        float acc[4][4];
        #pragma unroll
        for (int i = 0; i < 4; i++)
            #pragma unroll
            for (int j = 0; j < 4; j++) acc[i][j] = 0.0f;

        #pragma unroll
        for (int d4 = 0; d4 < 16; d4++) {
            float4 q4[4], k4[4];
            #pragma unroll
            for (int i = 0; i < 4; i++) q4[i] = *(const float4*)&Qs[q0 + i][d4 * 4];
            #pragma unroll
            for (int j = 0; j < 4; j++) k4[j] = *(const float4*)&KV[j * 16 + tx][4 * (d4 ^ tx)];
            #pragma unroll
            for (int i = 0; i < 4; i++)
                #pragma unroll
                for (int j = 0; j < 4; j++) {
                    acc[i][j] = fmaf(q4[i].x, k4[j].x, acc[i][j]);
                    acc[i][j] = fmaf(q4[i].y, k4[j].y, acc[i][j]);
                    acc[i][j] = fmaf(q4[i].z, k4[j].z, acc[i][j]);
                    acc[i][j] = fmaf(q4[i].w, k4[j].w, acc[i][j]);
                }
        }

        // causal mask (last tile only)
        if (kt == nkt - 1) {
            #pragma unroll
            for (int i = 0; i < 4; i++)
                #pragma unroll
                for (int j = 0; j < 4; j++)
                    if (k0 + j * 16 + tx > qg0 + q0 + i) acc[i][j] = NEG_BIG;
        }

        // ---- online softmax: reductions across the 16 tx lanes ----
        #pragma unroll
        for (int i = 0; i < 4; i++) {
            float rmax = fmaxf(fmaxf(acc[i][0], acc[i][1]), fmaxf(acc[i][2], acc[i][3]));
            rmax = fmaxf(rmax, __shfl_xor_sync(0xffffffffu, rmax, 1));
            rmax = fmaxf(rmax, __shfl_xor_sync(0xffffffffu, rmax, 2));
            rmax = fmaxf(rmax, __shfl_xor_sync(0xffffffffu, rmax, 4));
            rmax = fmaxf(rmax, __shfl_xor_sync(0xffffffffu, rmax, 8));

            const float m_new = fmaxf(m_run[i], rmax);
            const float alpha = __expf(m_run[i] - m_new);

            float psum = 0.0f;
            #pragma unroll
            for (int j = 0; j < 4; j++) {
                const float p = __expf(acc[i][j] - m_new);
                acc[i][j] = p;
                psum += p;
            }
            psum += __shfl_xor_sync(0xffffffffu, psum, 1);
            psum += __shfl_xor_sync(0xffffffffu, psum, 2);
            psum += __shfl_xor_sync(0xffffffffu, psum, 4);
            psum += __shfl_xor_sync(0xffffffffu, psum, 8);

            l_run[i] = l_run[i] * alpha + psum;
            m_run[i] = m_new;
            #pragma unroll
            for (int c = 0; c < 4; c++) O[i][c] *= alpha;
        }

        // publish P (transposed to [key][q])
        #pragma unroll
        for (int i = 0; i < 4; i++)
            #pragma unroll
            for (int j = 0; j < 4; j++)
                Ps[j * 16 + tx][q0 + i] = acc[i][j];
        __syncthreads();   // sync_c: scores done reading K; Ps published

        // write V registers into KV (plain layout)
        #pragma unroll
        for (int it = 0; it < 8; it++) {
            const int idx = tid + it * 128;
            *(float4*)&KV[idx >> 4][(idx & 15) * 4] = vreg[it];
        }
        __syncthreads();   // sync_d: V tile ready

        // ---- PV: O[4 q][4 h], h cols = tx*4..tx*4+3, all 64 keys ----
        #pragma unroll 8
        for (int j = 0; j < TK; j++) {
            const float4 p4 = *(const float4*)&Ps[j][q0];
            const float4 v4 = *(const float4*)&KV[j][tx * 4];
            const float pi[4] = { p4.x, p4.y, p4.z, p4.w };
            #pragma unroll
            for (int i = 0; i < 4; i++) {
                O[i][0] = fmaf(pi[i], v4.x, O[i][0]);
                O[i][1] = fmaf(pi[i], v4.y, O[i][1]);
                O[i][2] = fmaf(pi[i], v4.z, O[i][2]);
                O[i][3] = fmaf(pi[i], v4.w, O[i][3]);
            }
        }
    }

    // epilogue: normalize and store
    #pragma unroll
    for (int i = 0; i < 4; i++) {
        const float inv = 1.0f / l_run[i];
        float4 o;
        o.x = O[i][0] * inv; o.y = O[i][1] * inv;
        o.z = O[i][2] * inv; o.w = O[i][3] * inv;
        *(float4*)&zout[base + (size_t)(qg0 + q0 + i) * HEAD + tx * 4] = o;
    }
}

// ---------------------------------------------------------------------------
extern "C" void kernel_launch(void* const* d_in, const int* in_sizes, int n_in,
                              void* d_out, int out_size)
{
    const float* x  = (const float*)d_in[0];
    const float* Wk = (const float*)d_in[1];
    const float* Wq = (const float*)d_in[2];
    const float* Wv = (const float*)d_in[3];
    float* z = (float*)d_out;
    (void)in_sizes; (void)n_in; (void)out_size;

    dim3 pgrid(MROWS / 128, 3);
    proj_kernel<<<pgrid, 128>>>(x, Wk, Wq, Wv);

    dim3 agrid(NQT, BATCH);
    attn_kernel<<<agrid, 128>>>(z);
}

// round 5
// speedup vs baseline: 1.4824x; 1.0521x over previous
#include <cuda_runtime.h>
#include <math.h>

#define BATCH 8
#define SEQ   2048
#define DIM   1024
#define HEAD  64
#define MROWS (BATCH * SEQ)      // 16384
#define BQ  32
#define TK  64
#define NQT (SEQ / BQ)           // 64
#define NEG_BIG (-3.0e38f)

// d4/swizzle helper: v in 0..15 -> v ^ ((v>>3)<<2)  (bit3 folded into bit2)
#define SWZ(v) ((v) ^ (((v) >> 3) << 2))

// Scratch for Q, K, V projections (no allocation allowed -> device globals)
__device__ float g_Q[MROWS * HEAD];
__device__ float g_K[MROWS * HEAD];
__device__ float g_V[MROWS * HEAD];

// ---------------- packed f32x2 helpers (Blackwell FFMA2) ----------------
#define FMA2(d, a, b, c) \
    asm("fma.rn.f32x2 %0, %1, %2, %3;" : "=l"(d) : "l"(a), "l"(b), "l"(c))
#define MUL2(d, a, b) \
    asm("mul.rn.f32x2 %0, %1, %2;" : "=l"(d) : "l"(a), "l"(b))

__device__ __forceinline__ unsigned long long pack2(float x) {
    unsigned long long r;
    unsigned u = __float_as_uint(x);
    asm("mov.b64 %0, {%1, %1};" : "=l"(r) : "r"(u));
    return r;
}
__device__ __forceinline__ float2 unpack2(unsigned long long v) {
    unsigned a, b;
    asm("mov.b64 {%0, %1}, %2;" : "=r"(a), "=r"(b) : "l"(v));
    return make_float2(__uint_as_float(a), __uint_as_float(b));
}

// ---------------------------------------------------------------------------
// Kernel 1: QKV projection with FFMA2 (unchanged from R4 — passed, near floor)
// ---------------------------------------------------------------------------
__global__ __launch_bounds__(128, 4)
void proj_kernel(const float* __restrict__ x,
                 const float* __restrict__ Wk,
                 const float* __restrict__ Wq,
                 const float* __restrict__ Wv)
{
    __shared__ float Xs[128][36];
    __shared__ float Ws[32][68];

    const int tid  = threadIdx.x;
    const int tx   = tid & 7;
    const int ty   = tid >> 3;
    const int row0 = blockIdx.x * 128;

    const float* W;
    float* out;
    if (blockIdx.y == 0)      { W = Wq; out = g_Q; }
    else if (blockIdx.y == 1) { W = Wk; out = g_K; }
    else                      { W = Wv; out = g_V; }

    unsigned long long acc2[8][4];
    #pragma unroll
    for (int i = 0; i < 8; i++)
        #pragma unroll
        for (int p = 0; p < 4; p++) acc2[i][p] = 0ULL;

    for (int k0 = 0; k0 < DIM; k0 += 32) {
        #pragma unroll
        for (int it = 0; it < 8; it++) {
            const int idx = tid + it * 128;
            const int r   = idx >> 3;
            const int seg = idx & 7;
            *(float4*)&Xs[r][seg * 4] =
                *(const float4*)&x[(size_t)(row0 + r) * DIM + k0 + seg * 4];
        }
        #pragma unroll
        for (int it = 0; it < 4; it++) {
            const int idx = tid + it * 128;
            const int kk  = idx >> 4;
            const int seg = idx & 15;
            *(float4*)&Ws[kk][seg * 4] =
                *(const float4*)&W[(size_t)(k0 + kk) * HEAD + seg * 4];
        }
        __syncthreads();

        #pragma unroll 16
        for (int kk = 0; kk < 32; kk++) {
            unsigned long long b[4];
            #pragma unroll
            for (int p = 0; p < 4; p++)
                b[p] = *(const unsigned long long*)&Ws[kk][tx * 8 + 2 * p];
            #pragma unroll
            for (int i = 0; i < 8; i++) {
                unsigned long long aa = pack2(Xs[ty + 16 * i][kk]);
                #pragma unroll
                for (int p = 0; p < 4; p++)
                    FMA2(acc2[i][p], aa, b[p], acc2[i][p]);
            }
        }
        __syncthreads();
    }

    #pragma unroll
    for (int i = 0; i < 8; i++) {
        float2 f0 = unpack2(acc2[i][0]);
        float2 f1 = unpack2(acc2[i][1]);
        float2 f2 = unpack2(acc2[i][2]);
        float2 f3 = unpack2(acc2[i][3]);
        const size_t rb = (size_t)(row0 + ty + 16 * i) * HEAD + tx * 8;
        float4 o1; o1.x = f0.x; o1.y = f0.y; o1.z = f1.x; o1.w = f1.y;
        float4 o2; o2.x = f2.x; o2.y = f2.y; o2.z = f3.x; o2.w = f3.y;
        *(float4*)&out[rb]     = o1;
        *(float4*)&out[rb + 4] = o2;
    }
}

// ---------------------------------------------------------------------------
// Kernel 2: fused causal flash attention, v3.
// 128 threads: warp(=ty) 0..3 owns 8 queries; lane = tx(4b)<<1 | dz(1b).
//   scores: thread computes 8q x 4k (keys 4*tx..+3) over its d-half (dz),
//           partials merged via shfl_xor(1).  1.5 B smem per MAC.
//   PV:     FFMA2, 8q x 4h (h = 4*tx..+3), keys split by dz (32 each),
//           O halves summed once at block end via 64-bit shfl.
// All smem layouts swizzled so dz-lane pairs never alias banks.
// ---------------------------------------------------------------------------
__global__ __launch_bounds__(128, 3)
void attn_kernel(float* __restrict__ zout)
{
    __shared__ float Qs[BQ][64];   // (q, d4-chunk) at col 4*SWZ(d4)
    __shared__ float KV[TK][64];   // (key, d4)     at col 4*(SWZ(d4) ^ (key>>2))
    __shared__ float Vs[TK][64];   // (key, d4)     at col 4*(d4 ^ ((key>>5)<<2))
    __shared__ float Ps[BQ][64];   // (q, key)      at col  key ^ ((key>>5)<<2)

    const int tid  = threadIdx.x;
    const int lane = tid & 31;
    const int warp = tid >> 5;      // 0..3
    const int dz   = lane & 1;      // d-half (scores) / key-half (PV)
    const int tx   = lane >> 1;     // 0..15
    const int q0   = warp * 8;

    const int qt  = (NQT - 1) - blockIdx.x;   // heavy-first
    const int b   = blockIdx.y;
    const size_t base = (size_t)b * SEQ * HEAD;
    const int qg0 = qt * BQ;

    // Q tile -> smem (pre-scaled by 1/8), swizzled columns
    #pragma unroll
    for (int it = 0; it < 4; it++) {
        const int idx = tid + it * 128;
        const int r   = idx >> 4;
        const int d4  = idx & 15;
        float4 v = *(const float4*)&g_Q[base + (size_t)(qg0 + r) * HEAD + d4 * 4];
        v.x *= 0.125f; v.y *= 0.125f; v.z *= 0.125f; v.w *= 0.125f;
        *(float4*)&Qs[r][4 * SWZ(d4)] = v;
    }

    unsigned long long O2[8][2];    // (q i, h-pair) packed f32x2
    float m_run[8], l_run[8];
    #pragma unroll
    for (int i = 0; i < 8; i++) {
        m_run[i] = NEG_BIG; l_run[i] = 0.0f;
        O2[i][0] = 0ULL; O2[i][1] = 0ULL;
    }

    const int nkt = qt / 2 + 1;

    #pragma unroll 1
    for (int kt = 0; kt < nkt; kt++) {
        const int k0 = kt * TK;
        __syncthreads();   // sync_a: previous PV done reading KV/Vs/Ps

        // load K (score-swizzled) and V (PV-swizzled)
        #pragma unroll
        for (int it = 0; it < 8; it++) {
            const int idx = tid + it * 128;
            const int key = idx >> 4;
            const int d4  = idx & 15;
            *(float4*)&KV[key][4 * (SWZ(d4) ^ (key >> 2))] =
                *(const float4*)&g_K[base + (size_t)(k0 + key) * HEAD + d4 * 4];
            *(float4*)&Vs[key][4 * (d4 ^ ((key >> 5) << 2))] =
                *(const float4*)&g_V[base + (size_t)(k0 + key) * HEAD + d4 * 4];
        }
        __syncthreads();   // sync_b: tiles ready

        // ---- scores: 8q x 4k over this lane's d-half ----
        float acc[8][4];
        #pragma unroll
        for (int i = 0; i < 8; i++)
            #pragma unroll
            for (int c = 0; c < 4; c++) acc[i][c] = 0.0f;

        #pragma unroll
        for (int d4loc = 0; d4loc < 8; d4loc++) {
            const int sw4 = (dz << 3) | (d4loc ^ (dz << 2));   // = SWZ(dz*8+d4loc)
            float4 k4[4];
            #pragma unroll
            for (int c = 0; c < 4; c++)
                k4[c] = *(const float4*)&KV[4 * tx + c][4 * (sw4 ^ tx)];
            #pragma unroll
            for (int i = 0; i < 8; i++) {
                const float4 q4 = *(const float4*)&Qs[q0 + i][4 * sw4];
                #pragma unroll
                for (int c = 0; c < 4; c++) {
                    acc[i][c] = fmaf(q4.x, k4[c].x, acc[i][c]);
                    acc[i][c] = fmaf(q4.y, k4[c].y, acc[i][c]);
                    acc[i][c] = fmaf(q4.z, k4[c].z, acc[i][c]);
                    acc[i][c] = fmaf(q4.w, k4[c].w, acc[i][c]);
                }
            }
        }

        // merge d-halves (dz partner), mask, online softmax
        const bool lastTile = (kt == nkt - 1);
        #pragma unroll
        for (int i = 0; i < 8; i++) {
            float s[4];
            #pragma unroll
            for (int c = 0; c < 4; c++) {
                float v = acc[i][c];
                v += __shfl_xor_sync(0xffffffffu, v, 1);
                if (lastTile && (k0 + 4 * tx + c > qg0 + q0 + i)) v = NEG_BIG;
                s[c] = v;
            }
            float rmax = fmaxf(fmaxf(s[0], s[1]), fmaxf(s[2], s[3]));
            rmax = fmaxf(rmax, __shfl_xor_sync(0xffffffffu, rmax, 2));
            rmax = fmaxf(rmax, __shfl_xor_sync(0xffffffffu, rmax, 4));
            rmax = fmaxf(rmax, __shfl_xor_sync(0xffffffffu, rmax, 8));
            rmax = fmaxf(rmax, __shfl_xor_sync(0xffffffffu, rmax, 16));

            const float m_new = fmaxf(m_run[i], rmax);
            const float alpha = __expf(m_run[i] - m_new);

            float p[4], psum = 0.0f;
            #pragma unroll
            for (int c = 0; c < 4; c++) { p[c] = __expf(s[c] - m_new); psum += p[c]; }
            psum += __shfl_xor_sync(0xffffffffu, psum, 2);
            psum += __shfl_xor_sync(0xffffffffu, psum, 4);
            psum += __shfl_xor_sync(0xffffffffu, psum, 8);
            psum += __shfl_xor_sync(0xffffffffu, psum, 16);

            l_run[i] = l_run[i] * alpha + psum;
            m_run[i] = m_new;

            const unsigned long long a2 = pack2(alpha);
            MUL2(O2[i][0], O2[i][0], a2);
            MUL2(O2[i][1], O2[i][1], a2);

            if (dz == 0) {
                float4 p4; p4.x = p[0]; p4.y = p[1]; p4.z = p[2]; p4.w = p[3];
                *(float4*)&Ps[q0 + i][(4 * tx) ^ ((tx >> 3) << 2)] = p4;
            }
        }
        __syncthreads();   // sync_c: K reads done, Ps published

        // ---- PV (FFMA2): 8q x 4h, keys dz*32 .. dz*32+31 ----
        #pragma unroll
        for (int jb = 0; jb < 8; jb++) {
            const int j0    = dz * 32 + jb * 4;
            const int pbase = dz * 32 + 4 * (jb ^ dz);           // Ps swizzled col
            float4 pf[8];
            #pragma unroll
            for (int i = 0; i < 8; i++)
                pf[i] = *(const float4*)&Ps[q0 + i][pbase];
            unsigned long long v2[4][2];
            #pragma unroll
            for (int jj = 0; jj < 4; jj++) {
                const float4 vv = *(const float4*)&Vs[j0 + jj][4 * (tx ^ (dz << 2))];
                v2[jj][0] = *(const unsigned long long*)&vv.x;
                v2[jj][1] = *(const unsigned long long*)&vv.z;
            }
            #pragma unroll
            for (int i = 0; i < 8; i++) {
                const float pv[4] = { pf[i].x, pf[i].y, pf[i].z, pf[i].w };
                #pragma unroll
                for (int jj = 0; jj < 4; jj++) {
                    const unsigned long long pp = pack2(pv[jj]);
                    FMA2(O2[i][0], pp, v2[jj][0], O2[i][0]);
                    FMA2(O2[i][1], pp, v2[jj][1], O2[i][1]);
                }
            }
        }
    }

    // combine dz key-halves of O, normalize, store (rows split by dz)
    #pragma unroll
    for (int i = 0; i < 8; i++) {
        O2[i][0] += 0ULL;  // keep as u64 for shfl
        unsigned long long o0 = O2[i][0], o1 = O2[i][1];
        o0 = o0; o1 = o1;
        unsigned long long p0 = __shfl_xor_sync(0xffffffffu, O2[i][0], 1);
        unsigned long long p1 = __shfl_xor_sync(0xffffffffu, O2[i][1], 1);
        float2 a0 = unpack2(O2[i][0]), b0 = unpack2(p0);
        float2 a1 = unpack2(O2[i][1]), b1 = unpack2(p1);
        const float inv = 1.0f / l_run[i];
        float4 o;
        o.x = (a0.x + b0.x) * inv; o.y = (a0.y + b0.y) * inv;
        o.z = (a1.x + b1.x) * inv; o.w = (a1.y + b1.y) * inv;
        if ((i >> 2) == dz)   // dz=0 stores i 0..3, dz=1 stores i 4..7
            *(float4*)&zout[base + (size_t)(qg0 + q0 + i) * HEAD + 4 * tx] = o;
    }
}

// ---------------------------------------------------------------------------
extern "C" void kernel_launch(void* const* d_in, const int* in_sizes, int n_in,
                              void* d_out, int out_size)
{
    const float* x  = (const float*)d_in[0];
    const float* Wk = (const float*)d_in[1];
    const float* Wq = (const float*)d_in[2];
    const float* Wv = (const float*)d_in[3];
    float* z = (float*)d_out;
    (void)in_sizes; (void)n_in; (void)out_size;

    dim3 pgrid(MROWS / 128, 3);
    proj_kernel<<<pgrid, 128>>>(x, Wk, Wq, Wv);

    dim3 agrid(NQT, BATCH);
    attn_kernel<<<agrid, 128>>>(z);
}

// round 6
// speedup vs baseline: 3.1033x; 2.0934x over previous
#include <cuda_runtime.h>
#include <math.h>

#define BATCH 8
#define SEQ   2048
#define DIM   1024
#define HEAD  64
#define MROWS (BATCH * SEQ)      // 16384
#define BQ  64
#define TK  64
#define NQT2 (SEQ / BQ)          // 32
#define NEG_BIG (-3.0e38f)

// Scratch for Q, K, V projections (no allocation allowed -> device globals)
__device__ float g_Q[MROWS * HEAD];
__device__ float g_K[MROWS * HEAD];
__device__ float g_V[MROWS * HEAD];

// ---------------- tf32 helpers ----------------
__device__ __forceinline__ unsigned f2tf(float x) {
    unsigned r;
    asm("cvt.rna.tf32.f32 %0, %1;" : "=r"(r) : "f"(x));
    return r;
}

// D(16x8,f32) += A(16x8,tf32,row) * B(8x8,tf32,col)
__device__ __forceinline__ void mma_tf32(float d[4], const unsigned a[4], const unsigned b[2]) {
    asm("mma.sync.aligned.m16n8k8.row.col.f32.tf32.tf32.f32 "
        "{%0,%1,%2,%3}, {%4,%5,%6,%7}, {%8,%9}, {%0,%1,%2,%3};"
        : "+f"(d[0]), "+f"(d[1]), "+f"(d[2]), "+f"(d[3])
        : "r"(a[0]), "r"(a[1]), "r"(a[2]), "r"(a[3]), "r"(b[0]), "r"(b[1]));
}

// ---------------------------------------------------------------------------
// Kernel 1: QKV projection, tf32 tensor cores.
// C[16384,64] = X[16384,1024] @ W[1024,64].  128 thr / 4 warps; block tile
// M=64 (16 rows per warp), N=64, K-chunk 32.
// Xs stride 36 (=4 mod 32): A-frag reads conflict-free (bank 4g+c).
// Ws stride 72 (=8 mod 32): B-frag reads conflict-free (bank 8c+g).
// ---------------------------------------------------------------------------
__global__ __launch_bounds__(128, 4)
void proj_kernel(const float* __restrict__ x,
                 const float* __restrict__ Wk,
                 const float* __restrict__ Wq,
                 const float* __restrict__ Wv)
{
    __shared__ unsigned Xs[64][36];   // tf32 bits
    __shared__ unsigned Ws[32][72];   // tf32 bits

    const int tid  = threadIdx.x;
    const int warp = tid >> 5;
    const int lane = tid & 31;
    const int g    = lane >> 2;   // 0..7
    const int c    = lane & 3;    // 0..3
    const int row0 = blockIdx.x * 64;

    const float* W;
    float* out;
    if (blockIdx.y == 0)      { W = Wq; out = g_Q; }
    else if (blockIdx.y == 1) { W = Wk; out = g_K; }
    else                      { W = Wv; out = g_V; }

    float acc[8][4];
    #pragma unroll
    for (int nt = 0; nt < 8; nt++)
        #pragma unroll
        for (int j = 0; j < 4; j++) acc[nt][j] = 0.0f;

    for (int k0 = 0; k0 < DIM; k0 += 32) {
        // X tile: 64 rows x 32 k = 512 float4
        #pragma unroll
        for (int it = 0; it < 4; it++) {
            const int idx = tid + it * 128;
            const int r   = idx >> 3;
            const int s   = idx & 7;
            float4 v = *(const float4*)&x[(size_t)(row0 + r) * DIM + k0 + s * 4];
            uint4 u; u.x = f2tf(v.x); u.y = f2tf(v.y); u.z = f2tf(v.z); u.w = f2tf(v.w);
            *(uint4*)&Xs[r][s * 4] = u;
        }
        // W tile: 32 k x 64 n = 512 float4
        #pragma unroll
        for (int it = 0; it < 4; it++) {
            const int idx = tid + it * 128;
            const int r   = idx >> 4;
            const int s   = idx & 15;
            float4 v = *(const float4*)&W[(size_t)(k0 + r) * HEAD + s * 4];
            uint4 u; u.x = f2tf(v.x); u.y = f2tf(v.y); u.z = f2tf(v.z); u.w = f2tf(v.w);
            *(uint4*)&Ws[r][s * 4] = u;
        }
        __syncthreads();

        #pragma unroll
        for (int ks = 0; ks < 4; ks++) {
            unsigned a[4];
            a[0] = Xs[16 * warp + g][ks * 8 + c];
            a[1] = Xs[16 * warp + g + 8][ks * 8 + c];
            a[2] = Xs[16 * warp + g][ks * 8 + c + 4];
            a[3] = Xs[16 * warp + g + 8][ks * 8 + c + 4];
            #pragma unroll
            for (int nt = 0; nt < 8; nt++) {
                unsigned b[2];
                b[0] = Ws[ks * 8 + c][nt * 8 + g];
                b[1] = Ws[ks * 8 + c + 4][nt * 8 + g];
                mma_tf32(acc[nt], a, b);
            }
        }
        __syncthreads();
    }

    // store: rows 16w+g, 16w+g+8; cols nt*8 + 2c (+1)
    #pragma unroll
    for (int nt = 0; nt < 8; nt++) {
        float2 lo; lo.x = acc[nt][0]; lo.y = acc[nt][1];
        float2 hi; hi.x = acc[nt][2]; hi.y = acc[nt][3];
        *(float2*)&out[(size_t)(row0 + 16 * warp + g)     * HEAD + nt * 8 + 2 * c] = lo;
        *(float2*)&out[(size_t)(row0 + 16 * warp + g + 8) * HEAD + nt * 8 + 2 * c] = hi;
    }
}

// ---------------------------------------------------------------------------
// Kernel 2: fused causal flash attention, tf32 tensor cores.
// 128 thr / 4 warps; BQ=64 (16 q-rows per warp), TK=64 keys/tile.
// Q held in registers as A-fragments for the whole block.
// Ks (stride 68 = 4 mod 32): B-frag reads bank 4g+c, conflict-free; reused
// as the P buffer after sync_c (A-frag reads also conflict-free).
// Vs (stride 72 = 8 mod 32): B-frag reads bank 8c+g, conflict-free.
// ---------------------------------------------------------------------------
__global__ __launch_bounds__(128)
void attn_kernel(float* __restrict__ zout)
{
    __shared__ unsigned Ks[64][68];   // K tf32 bits; P tf32 bits after scores
    __shared__ unsigned Vs[64][72];   // V tf32 bits

    const int tid  = threadIdx.x;
    const int warp = tid >> 5;
    const int lane = tid & 31;
    const int g    = lane >> 2;
    const int c    = lane & 3;

    const int qt  = (NQT2 - 1) - blockIdx.x;   // heavy-first
    const int b   = blockIdx.y;
    const size_t base = (size_t)b * SEQ * HEAD;
    const int qg0   = qt * BQ;
    const int qrow0 = qg0 + 16 * warp;         // warp's q rows: qrow0+g, qrow0+g+8

    // Q A-fragments (pre-scaled by 1/8, tf32) — registers, whole block lifetime
    unsigned Qf[8][4];
    #pragma unroll
    for (int ks = 0; ks < 8; ks++) {
        Qf[ks][0] = f2tf(0.125f * g_Q[base + (size_t)(qrow0 + g)     * HEAD + ks * 8 + c]);
        Qf[ks][1] = f2tf(0.125f * g_Q[base + (size_t)(qrow0 + g + 8) * HEAD + ks * 8 + c]);
        Qf[ks][2] = f2tf(0.125f * g_Q[base + (size_t)(qrow0 + g)     * HEAD + ks * 8 + c + 4]);
        Qf[ks][3] = f2tf(0.125f * g_Q[base + (size_t)(qrow0 + g + 8) * HEAD + ks * 8 + c + 4]);
    }

    float O[8][4];
    #pragma unroll
    for (int nt = 0; nt < 8; nt++)
        #pragma unroll
        for (int j = 0; j < 4; j++) O[nt][j] = 0.0f;
    float mrun[2] = { NEG_BIG, NEG_BIG };
    float lrun[2] = { 0.0f, 0.0f };

    const int nkt = qt + 1;

    #pragma unroll 1
    for (int kt = 0; kt < nkt; kt++) {
        const int k0 = kt * TK;
        __syncthreads();   // sync_a: prev PV done reading Ks(P)/Vs

        // load K, V tiles (64x64 each), convert to tf32
        #pragma unroll
        for (int it = 0; it < 8; it++) {
            const int idx = tid + it * 128;
            const int key = idx >> 4;
            const int d4  = idx & 15;
            float4 kv = *(const float4*)&g_K[base + (size_t)(k0 + key) * HEAD + d4 * 4];
            uint4 ku; ku.x = f2tf(kv.x); ku.y = f2tf(kv.y); ku.z = f2tf(kv.z); ku.w = f2tf(kv.w);
            *(uint4*)&Ks[key][d4 * 4] = ku;
            float4 vv = *(const float4*)&g_V[base + (size_t)(k0 + key) * HEAD + d4 * 4];
            uint4 vu; vu.x = f2tf(vv.x); vu.y = f2tf(vv.y); vu.z = f2tf(vv.z); vu.w = f2tf(vv.w);
            *(uint4*)&Vs[key][d4 * 4] = vu;
        }
        __syncthreads();   // sync_b: tiles ready

        // ---- scores: S[16q x 64key] per warp ----
        float S[8][4];
        #pragma unroll
        for (int nt = 0; nt < 8; nt++)
            #pragma unroll
            for (int j = 0; j < 4; j++) S[nt][j] = 0.0f;

        #pragma unroll
        for (int ks = 0; ks < 8; ks++) {
            #pragma unroll
            for (int nt = 0; nt < 8; nt++) {
                unsigned bf[2];
                bf[0] = Ks[nt * 8 + g][ks * 8 + c];
                bf[1] = Ks[nt * 8 + g][ks * 8 + c + 4];
                mma_tf32(S[nt], Qf[ks], bf);
            }
        }

        // causal mask (diagonal tile only: kt == qt)
        if (kt == nkt - 1) {
            #pragma unroll
            for (int nt = 0; nt < 8; nt++)
                #pragma unroll
                for (int j = 0; j < 4; j++) {
                    const int col = k0 + nt * 8 + 2 * c + (j & 1);
                    const int row = qrow0 + g + ((j >= 2) ? 8 : 0);
                    if (col > row) S[nt][j] = NEG_BIG;
                }
        }

        // ---- online softmax (rows g and g+8) ----
        float mx0 = NEG_BIG, mx1 = NEG_BIG;
        #pragma unroll
        for (int nt = 0; nt < 8; nt++) {
            mx0 = fmaxf(mx0, fmaxf(S[nt][0], S[nt][1]));
            mx1 = fmaxf(mx1, fmaxf(S[nt][2], S[nt][3]));
        }
        mx0 = fmaxf(mx0, __shfl_xor_sync(0xffffffffu, mx0, 1));
        mx0 = fmaxf(mx0, __shfl_xor_sync(0xffffffffu, mx0, 2));
        mx1 = fmaxf(mx1, __shfl_xor_sync(0xffffffffu, mx1, 1));
        mx1 = fmaxf(mx1, __shfl_xor_sync(0xffffffffu, mx1, 2));

        const float mn0 = fmaxf(mrun[0], mx0);
        const float mn1 = fmaxf(mrun[1], mx1);
        const float al0 = __expf(mrun[0] - mn0);
        const float al1 = __expf(mrun[1] - mn1);

        float ps0 = 0.0f, ps1 = 0.0f;
        #pragma unroll
        for (int nt = 0; nt < 8; nt++) {
            // round p to tf32 BEFORE accumulating l so bias cancels in O/l
            float p0 = __uint_as_float(f2tf(__expf(S[nt][0] - mn0)));
            float p1 = __uint_as_float(f2tf(__expf(S[nt][1] - mn0)));
            float p2 = __uint_as_float(f2tf(__expf(S[nt][2] - mn1)));
            float p3 = __uint_as_float(f2tf(__expf(S[nt][3] - mn1)));
            S[nt][0] = p0; S[nt][1] = p1; S[nt][2] = p2; S[nt][3] = p3;
            ps0 += p0 + p1;
            ps1 += p2 + p3;
        }
        ps0 += __shfl_xor_sync(0xffffffffu, ps0, 1);
        ps0 += __shfl_xor_sync(0xffffffffu, ps0, 2);
        ps1 += __shfl_xor_sync(0xffffffffu, ps1, 1);
        ps1 += __shfl_xor_sync(0xffffffffu, ps1, 2);

        lrun[0] = lrun[0] * al0 + ps0;
        lrun[1] = lrun[1] * al1 + ps1;
        mrun[0] = mn0;
        mrun[1] = mn1;
        #pragma unroll
        for (int nt = 0; nt < 8; nt++) {
            O[nt][0] *= al0; O[nt][1] *= al0;
            O[nt][2] *= al1; O[nt][3] *= al1;
        }

        __syncthreads();   // sync_c: ALL warps done reading K before P overwrite

        // publish P into Ks buffer (warp-private rows 16w..16w+15)
        #pragma unroll
        for (int nt = 0; nt < 8; nt++) {
            uint2 lo; lo.x = __float_as_uint(S[nt][0]); lo.y = __float_as_uint(S[nt][1]);
            uint2 hi; hi.x = __float_as_uint(S[nt][2]); hi.y = __float_as_uint(S[nt][3]);
            *(uint2*)&Ks[16 * warp + g][nt * 8 + 2 * c]     = lo;
            *(uint2*)&Ks[16 * warp + g + 8][nt * 8 + 2 * c] = hi;
        }
        __syncwarp();

        // ---- PV: O[16q x 64d] += P[16q x 64key] * V[64key x 64d] ----
        #pragma unroll
        for (int kp = 0; kp < 8; kp++) {
            unsigned a[4];
            a[0] = Ks[16 * warp + g][kp * 8 + c];
            a[1] = Ks[16 * warp + g + 8][kp * 8 + c];
            a[2] = Ks[16 * warp + g][kp * 8 + c + 4];
            a[3] = Ks[16 * warp + g + 8][kp * 8 + c + 4];
            #pragma unroll
            for (int nt = 0; nt < 8; nt++) {
                unsigned bf[2];
                bf[0] = Vs[kp * 8 + c][nt * 8 + g];
                bf[1] = Vs[kp * 8 + c + 4][nt * 8 + g];
                mma_tf32(O[nt], a, bf);
            }
        }
    }

    // epilogue: normalize, store
    const float inv0 = 1.0f / lrun[0];
    const float inv1 = 1.0f / lrun[1];
    #pragma unroll
    for (int nt = 0; nt < 8; nt++) {
        float2 lo; lo.x = O[nt][0] * inv0; lo.y = O[nt][1] * inv0;
        float2 hi; hi.x = O[nt][2] * inv1; hi.y = O[nt][3] * inv1;
        *(float2*)&zout[base + (size_t)(qrow0 + g)     * HEAD + nt * 8 + 2 * c] = lo;
        *(float2*)&zout[base + (size_t)(qrow0 + g + 8) * HEAD + nt * 8 + 2 * c] = hi;
    }
}

// ---------------------------------------------------------------------------
extern "C" void kernel_launch(void* const* d_in, const int* in_sizes, int n_in,
                              void* d_out, int out_size)
{
    const float* x  = (const float*)d_in[0];
    const float* Wk = (const float*)d_in[1];
    const float* Wq = (const float*)d_in[2];
    const float* Wv = (const float*)d_in[3];
    float* z = (float*)d_out;
    (void)in_sizes; (void)n_in; (void)out_size;

    dim3 pgrid(MROWS / 64, 3);
    proj_kernel<<<pgrid, 128>>>(x, Wk, Wq, Wv);

    dim3 agrid(NQT2, BATCH);
    attn_kernel<<<agrid, 128>>>(z);
}

// round 8
// speedup vs baseline: 4.0936x; 1.3191x over previous
#include <cuda_runtime.h>
#include <math.h>

#define BATCH 8
#define SEQ   2048
#define DIM   1024
#define HEAD  64
#define MROWS (BATCH * SEQ)      // 16384
#define BQ  64
#define TK  64
#define NQT2 (SEQ / BQ)          // 32
#define NEG_BIG (-3.0e38f)

// Scratch (no allocation allowed -> device globals)
__device__ float g_Q[MROWS * HEAD];
__device__ float g_K[MROWS * HEAD];
__device__ float g_V[MROWS * HEAD];
__device__ float g_Op[2][MROWS * HEAD];   // split-K partial O (unnormalized)
__device__ float g_m[2][MROWS];           // split-K partial row max
__device__ float g_l[2][MROWS];           // split-K partial row sum

// ---------------- tf32 / async helpers ----------------
__device__ __forceinline__ unsigned f2tf(float x) {
    unsigned r;
    asm("cvt.rna.tf32.f32 %0, %1;" : "=r"(r) : "f"(x));
    return r;
}

__device__ __forceinline__ void mma_tf32(float d[4], const unsigned a[4], const unsigned b[2]) {
    asm("mma.sync.aligned.m16n8k8.row.col.f32.tf32.tf32.f32 "
        "{%0,%1,%2,%3}, {%4,%5,%6,%7}, {%8,%9}, {%0,%1,%2,%3};"
        : "+f"(d[0]), "+f"(d[1]), "+f"(d[2]), "+f"(d[3])
        : "r"(a[0]), "r"(a[1]), "r"(a[2]), "r"(a[3]), "r"(b[0]), "r"(b[1]));
}

__device__ __forceinline__ void cp16(void* smem, const void* gptr) {
    unsigned s = (unsigned)__cvta_generic_to_shared(smem);
    asm volatile("cp.async.cg.shared.global [%0], [%1], 16;" :: "r"(s), "l"(gptr));
}
#define CP_COMMIT() asm volatile("cp.async.commit_group;")
#define CP_WAIT1()  asm volatile("cp.async.wait_group 1;")
#define CP_WAIT0()  asm volatile("cp.async.wait_group 0;")

// ---------------------------------------------------------------------------
// Kernel 1: QKV projection, tf32 MMA + cp.async 2-stage pipeline.
// 128 thr / 4 warps; tile M=64, N=64, k-chunk 16 (64 chunks).
// Raw fp32 staged in smem; tf32 cvt at fragment read.
// Xs stride 20 (=20 mod 32): a-frag banks 20g+c — bijective, conflict-free.
// Ws stride 72 (=8 mod 32):  b-frag banks 8c+g — bijective, conflict-free.
// ---------------------------------------------------------------------------
__global__ __launch_bounds__(128, 4)
void proj_kernel(const float* __restrict__ x,
                 const float* __restrict__ Wk,
                 const float* __restrict__ Wq,
                 const float* __restrict__ Wv)
{
    __shared__ float Xs[2][64][20];   // raw fp32, 64 rows x 16 k
    __shared__ float Ws[2][16][72];   // raw fp32, 16 k x 64 n

    const int tid  = threadIdx.x;
    const int warp = tid >> 5;
    const int lane = tid & 31;
    const int g    = lane >> 2;   // 0..7
    const int c    = lane & 3;    // 0..3
    const int row0 = blockIdx.x * 64;

    const float* W;
    float* out;
    if (blockIdx.y == 0)      { W = Wq; out = g_Q; }
    else if (blockIdx.y == 1) { W = Wk; out = g_K; }
    else                      { W = Wv; out = g_V; }

    // per-thread load indices (2 float4 each for X and W per chunk)
    const int xr0 = tid >> 2,            xs0 = tid & 3;
    const int xr1 = (tid + 128) >> 2,    xs1 = tid & 3;
    const int wr0 = tid >> 4,            ws0 = tid & 15;
    const int wr1 = (tid + 128) >> 4,    ws1 = tid & 15;

    float acc[8][4];
    #pragma unroll
    for (int nt = 0; nt < 8; nt++)
        #pragma unroll
        for (int j = 0; j < 4; j++) acc[nt][j] = 0.0f;

    // ---- prologue: issue chunk 0 into stage 0 ----
    {
        const int k0 = 0;
        cp16(&Xs[0][xr0][xs0 * 4], &x[(size_t)(row0 + xr0) * DIM + k0 + xs0 * 4]);
        cp16(&Xs[0][xr1][xs1 * 4], &x[(size_t)(row0 + xr1) * DIM + k0 + xs1 * 4]);
        cp16(&Ws[0][wr0][ws0 * 4], &W[(size_t)(k0 + wr0) * HEAD + ws0 * 4]);
        cp16(&Ws[0][wr1][ws1 * 4], &W[(size_t)(k0 + wr1) * HEAD + ws1 * 4]);
        CP_COMMIT();
    }

    #pragma unroll 1
    for (int ck = 0; ck < 64; ck++) {
        const int st = ck & 1;
        if (ck < 63) {
            const int k0 = (ck + 1) * 16;
            const int sn = st ^ 1;
            cp16(&Xs[sn][xr0][xs0 * 4], &x[(size_t)(row0 + xr0) * DIM + k0 + xs0 * 4]);
            cp16(&Xs[sn][xr1][xs1 * 4], &x[(size_t)(row0 + xr1) * DIM + k0 + xs1 * 4]);
            cp16(&Ws[sn][wr0][ws0 * 4], &W[(size_t)(k0 + wr0) * HEAD + ws0 * 4]);
            cp16(&Ws[sn][wr1][ws1 * 4], &W[(size_t)(k0 + wr1) * HEAD + ws1 * 4]);
            CP_COMMIT();
            CP_WAIT1();            // chunk ck complete
        } else {
            CP_WAIT0();
        }
        __syncthreads();           // stage st visible to all

        #pragma unroll
        for (int ks = 0; ks < 2; ks++) {
            unsigned a[4];
            a[0] = f2tf(Xs[st][16 * warp + g][ks * 8 + c]);
            a[1] = f2tf(Xs[st][16 * warp + g + 8][ks * 8 + c]);
            a[2] = f2tf(Xs[st][16 * warp + g][ks * 8 + c + 4]);
            a[3] = f2tf(Xs[st][16 * warp + g + 8][ks * 8 + c + 4]);
            #pragma unroll
            for (int nt = 0; nt < 8; nt++) {
                unsigned b[2];
                b[0] = f2tf(Ws[st][ks * 8 + c][nt * 8 + g]);
                b[1] = f2tf(Ws[st][ks * 8 + c + 4][nt * 8 + g]);
                mma_tf32(acc[nt], a, b);
            }
        }
        __syncthreads();           // compute done before stage st is re-filled
    }

    #pragma unroll
    for (int nt = 0; nt < 8; nt++) {
        float2 lo; lo.x = acc[nt][0]; lo.y = acc[nt][1];
        float2 hi; hi.x = acc[nt][2]; hi.y = acc[nt][3];
        *(float2*)&out[(size_t)(row0 + 16 * warp + g)     * HEAD + nt * 8 + 2 * c] = lo;
        *(float2*)&out[(size_t)(row0 + 16 * warp + g + 8) * HEAD + nt * 8 + 2 * c] = hi;
    }
}

// ---------------------------------------------------------------------------
// Kernel 2: fused causal flash attention, tf32, split-K over 2 blocks.
// grid (64, 8): bx -> (qt = 31 - (bx>>1), half = bx&1), heavy-first.
// Each block processes half the key tiles, writes unnormalized O + m,l.
// Tile internals identical to R6 (proven correct).
// ---------------------------------------------------------------------------
__global__ __launch_bounds__(128)
void attn_kernel()
{
    __shared__ unsigned Ks[64][68];   // K tf32 bits; P tf32 bits after scores
    __shared__ unsigned Vs[64][72];   // V tf32 bits

    const int tid  = threadIdx.x;
    const int warp = tid >> 5;
    const int lane = tid & 31;
    const int g    = lane >> 2;
    const int c    = lane & 3;

    const int qt   = (NQT2 - 1) - (blockIdx.x >> 1);   // heavy-first
    const int half = blockIdx.x & 1;
    const int b    = blockIdx.y;
    const size_t base = (size_t)b * SEQ * HEAD;
    const int qg0   = qt * BQ;
    const int qrow0 = qg0 + 16 * warp;

    const int nkt  = qt + 1;
    const int h    = (nkt + 1) >> 1;
    const int ktlo = half ? h : 0;
    const int kthi = half ? nkt : h;

    // Q A-fragments (pre-scaled by 1/8, tf32) — registers, whole block lifetime
    unsigned Qf[8][4];
    #pragma unroll
    for (int ks = 0; ks < 8; ks++) {
        Qf[ks][0] = f2tf(0.125f * g_Q[base + (size_t)(qrow0 + g)     * HEAD + ks * 8 + c]);
        Qf[ks][1] = f2tf(0.125f * g_Q[base + (size_t)(qrow0 + g + 8) * HEAD + ks * 8 + c]);
        Qf[ks][2] = f2tf(0.125f * g_Q[base + (size_t)(qrow0 + g)     * HEAD + ks * 8 + c + 4]);
        Qf[ks][3] = f2tf(0.125f * g_Q[base + (size_t)(qrow0 + g + 8) * HEAD + ks * 8 + c + 4]);
    }

    float O[8][4];
    #pragma unroll
    for (int nt = 0; nt < 8; nt++)
        #pragma unroll
        for (int j = 0; j < 4; j++) O[nt][j] = 0.0f;
    float mrun[2] = { NEG_BIG, NEG_BIG };
    float lrun[2] = { 0.0f, 0.0f };

    #pragma unroll 1
    for (int kt = ktlo; kt < kthi; kt++) {
        const int k0 = kt * TK;
        __syncthreads();   // sync_a: prev PV done reading Ks(P)/Vs

        #pragma unroll
        for (int it = 0; it < 8; it++) {
            const int idx = tid + it * 128;
            const int key = idx >> 4;
            const int d4  = idx & 15;
            float4 kv = *(const float4*)&g_K[base + (size_t)(k0 + key) * HEAD + d4 * 4];
            uint4 ku; ku.x = f2tf(kv.x); ku.y = f2tf(kv.y); ku.z = f2tf(kv.z); ku.w = f2tf(kv.w);
            *(uint4*)&Ks[key][d4 * 4] = ku;
            float4 vv = *(const float4*)&g_V[base + (size_t)(k0 + key) * HEAD + d4 * 4];
            uint4 vu; vu.x = f2tf(vv.x); vu.y = f2tf(vv.y); vu.z = f2tf(vv.z); vu.w = f2tf(vv.w);
            *(uint4*)&Vs[key][d4 * 4] = vu;
        }
        __syncthreads();   // sync_b: tiles ready

        // ---- scores ----
        float S[8][4];
        #pragma unroll
        for (int nt = 0; nt < 8; nt++)
            #pragma unroll
            for (int j = 0; j < 4; j++) S[nt][j] = 0.0f;

        #pragma unroll
        for (int ks = 0; ks < 8; ks++) {
            #pragma unroll
            for (int nt = 0; nt < 8; nt++) {
                unsigned bf[2];
                bf[0] = Ks[nt * 8 + g][ks * 8 + c];
                bf[1] = Ks[nt * 8 + g][ks * 8 + c + 4];
                mma_tf32(S[nt], Qf[ks], bf);
            }
        }

        // causal mask (diagonal tile)
        if (kt == qt) {
            #pragma unroll
            for (int nt = 0; nt < 8; nt++)
                #pragma unroll
                for (int j = 0; j < 4; j++) {
                    const int col = k0 + nt * 8 + 2 * c + (j & 1);
                    const int row = qrow0 + g + ((j >= 2) ? 8 : 0);
                    if (col > row) S[nt][j] = NEG_BIG;
                }
        }

        // ---- online softmax (rows g, g+8) ----
        float mx0 = NEG_BIG, mx1 = NEG_BIG;
        #pragma unroll
        for (int nt = 0; nt < 8; nt++) {
            mx0 = fmaxf(mx0, fmaxf(S[nt][0], S[nt][1]));
            mx1 = fmaxf(mx1, fmaxf(S[nt][2], S[nt][3]));
        }
        mx0 = fmaxf(mx0, __shfl_xor_sync(0xffffffffu, mx0, 1));
        mx0 = fmaxf(mx0, __shfl_xor_sync(0xffffffffu, mx0, 2));
        mx1 = fmaxf(mx1, __shfl_xor_sync(0xffffffffu, mx1, 1));
        mx1 = fmaxf(mx1, __shfl_xor_sync(0xffffffffu, mx1, 2));

        const float mn0 = fmaxf(mrun[0], mx0);
        const float mn1 = fmaxf(mrun[1], mx1);
        const float al0 = __expf(mrun[0] - mn0);
        const float al1 = __expf(mrun[1] - mn1);

        float ps0 = 0.0f, ps1 = 0.0f;
        #pragma unroll
        for (int nt = 0; nt < 8; nt++) {
            float p0 = __uint_as_float(f2tf(__expf(S[nt][0] - mn0)));
            float p1 = __uint_as_float(f2tf(__expf(S[nt][1] - mn0)));
            float p2 = __uint_as_float(f2tf(__expf(S[nt][2] - mn1)));
            float p3 = __uint_as_float(f2tf(__expf(S[nt][3] - mn1)));
            S[nt][0] = p0; S[nt][1] = p1; S[nt][2] = p2; S[nt][3] = p3;
            ps0 += p0 + p1;
            ps1 += p2 + p3;
        }
        ps0 += __shfl_xor_sync(0xffffffffu, ps0, 1);
        ps0 += __shfl_xor_sync(0xffffffffu, ps0, 2);
        ps1 += __shfl_xor_sync(0xffffffffu, ps1, 1);
        ps1 += __shfl_xor_sync(0xffffffffu, ps1, 2);

        lrun[0] = lrun[0] * al0 + ps0;
        lrun[1] = lrun[1] * al1 + ps1;
        mrun[0] = mn0;
        mrun[1] = mn1;
        #pragma unroll
        for (int nt = 0; nt < 8; nt++) {
            O[nt][0] *= al0; O[nt][1] *= al0;
            O[nt][2] *= al1; O[nt][3] *= al1;
        }

        __syncthreads();   // sync_c: all warps done reading K before P overwrite

        #pragma unroll
        for (int nt = 0; nt < 8; nt++) {
            uint2 lo; lo.x = __float_as_uint(S[nt][0]); lo.y = __float_as_uint(S[nt][1]);
            uint2 hi; hi.x = __float_as_uint(S[nt][2]); hi.y = __float_as_uint(S[nt][3]);
            *(uint2*)&Ks[16 * warp + g][nt * 8 + 2 * c]     = lo;
            *(uint2*)&Ks[16 * warp + g + 8][nt * 8 + 2 * c] = hi;
        }
        __syncwarp();

        // ---- PV ----
        #pragma unroll
        for (int kp = 0; kp < 8; kp++) {
            unsigned a[4];
            a[0] = Ks[16 * warp + g][kp * 8 + c];
            a[1] = Ks[16 * warp + g + 8][kp * 8 + c];
            a[2] = Ks[16 * warp + g][kp * 8 + c + 4];
            a[3] = Ks[16 * warp + g + 8][kp * 8 + c + 4];
            #pragma unroll
            for (int nt = 0; nt < 8; nt++) {
                unsigned bf[2];
                bf[0] = Vs[kp * 8 + c][nt * 8 + g];
                bf[1] = Vs[kp * 8 + c + 4][nt * 8 + g];
                mma_tf32(O[nt], a, bf);
            }
        }
    }

    // epilogue: write UNNORMALIZED partials + m,l for this half
    float* Op = g_Op[half];
    #pragma unroll
    for (int nt = 0; nt < 8; nt++) {
        float2 lo; lo.x = O[nt][0]; lo.y = O[nt][1];
        float2 hi; hi.x = O[nt][2]; hi.y = O[nt][3];
        *(float2*)&Op[base + (size_t)(qrow0 + g)     * HEAD + nt * 8 + 2 * c] = lo;
        *(float2*)&Op[base + (size_t)(qrow0 + g + 8) * HEAD + nt * 8 + 2 * c] = hi;
    }
    if (c == 0) {
        const int rg = b * SEQ + qrow0 + g;
        g_m[half][rg]     = mrun[0];
        g_l[half][rg]     = lrun[0];
        g_m[half][rg + 8] = mrun[1];
        g_l[half][rg + 8] = lrun[1];
    }
}

// ---------------------------------------------------------------------------
// Kernel 3: split-K combine.  z = (O0*w0 + O1*w1) / (l0*w0 + l1*w1),
// w_i = exp(m_i - max(m0,m1)).  Empty half has m=-BIG -> w=0 exactly.
// Block = 32 rows x 4 col-quarters (coalesced).
// ---------------------------------------------------------------------------
__global__ __launch_bounds__(128)
void combine_kernel(float* __restrict__ z)
{
    const int tid  = threadIdx.x;
    const int r    = blockIdx.x * 32 + (tid >> 2);
    const int part = tid & 3;

    const float m0 = g_m[0][r], m1 = g_m[1][r];
    const float l0 = g_l[0][r], l1 = g_l[1][r];
    const float M  = fmaxf(m0, m1);
    const float w0 = __expf(m0 - M);
    const float w1 = __expf(m1 - M);
    const float inv = 1.0f / (l0 * w0 + l1 * w1);

    const size_t rb = (size_t)r * HEAD + part * 16;
    #pragma unroll
    for (int d4 = 0; d4 < 4; d4++) {
        float4 a  = *(const float4*)&g_Op[0][rb + d4 * 4];
        float4 bq = *(const float4*)&g_Op[1][rb + d4 * 4];
        float4 o;
        o.x = (a.x * w0 + bq.x * w1) * inv;
        o.y = (a.y * w0 + bq.y * w1) * inv;
        o.z = (a.z * w0 + bq.z * w1) * inv;
        o.w = (a.w * w0 + bq.w * w1) * inv;
        *(float4*)&z[rb + d4 * 4] = o;
    }
}

// ---------------------------------------------------------------------------
extern "C" void kernel_launch(void* const* d_in, const int* in_sizes, int n_in,
                              void* d_out, int out_size)
{
    const float* x  = (const float*)d_in[0];
    const float* Wk = (const float*)d_in[1];
    const float* Wq = (const float*)d_in[2];
    const float* Wv = (const float*)d_in[3];
    float* z = (float*)d_out;
    (void)in_sizes; (void)n_in; (void)out_size;

    dim3 pgrid(MROWS / 64, 3);
    proj_kernel<<<pgrid, 128>>>(x, Wk, Wq, Wv);

    dim3 agrid(2 * NQT2, BATCH);
    attn_kernel<<<agrid, 128>>>();

    combine_kernel<<<MROWS / 32, 128>>>(z);
}

// round 9
// speedup vs baseline: 4.2185x; 1.0305x over previous
#include <cuda_runtime.h>
#include <math.h>

#define BATCH 8
#define SEQ   2048
#define DIM   1024
#define HEAD  64
#define MROWS (BATCH * SEQ)      // 16384
#define BQ  64
#define TK  64
#define NQT2 (SEQ / BQ)          // 32
#define NEG_BIG (-3.0e38f)

// Scratch (no allocation allowed -> device globals)
__device__ float g_Q[MROWS * HEAD];
__device__ float g_K[MROWS * HEAD];
__device__ float g_V[MROWS * HEAD];
__device__ unsigned g_Wt[3][DIM * HEAD];  // W pre-converted to tf32 bits (q,k,v)
__device__ float g_Op[2][MROWS * HEAD];   // split-K partial O (unnormalized)
__device__ float g_m[2][MROWS];           // split-K partial row max
__device__ float g_l[2][MROWS];           // split-K partial row sum

// ---------------- tf32 / async helpers ----------------
__device__ __forceinline__ unsigned f2tf(float x) {
    unsigned r;
    asm("cvt.rna.tf32.f32 %0, %1;" : "=r"(r) : "f"(x));
    return r;
}

__device__ __forceinline__ void mma_tf32(float d[4], const unsigned a[4], const unsigned b[2]) {
    asm("mma.sync.aligned.m16n8k8.row.col.f32.tf32.tf32.f32 "
        "{%0,%1,%2,%3}, {%4,%5,%6,%7}, {%8,%9}, {%0,%1,%2,%3};"
        : "+f"(d[0]), "+f"(d[1]), "+f"(d[2]), "+f"(d[3])
        : "r"(a[0]), "r"(a[1]), "r"(a[2]), "r"(a[3]), "r"(b[0]), "r"(b[1]));
}

__device__ __forceinline__ void cp16(void* smem, const void* gptr) {
    unsigned s = (unsigned)__cvta_generic_to_shared(smem);
    asm volatile("cp.async.cg.shared.global [%0], [%1], 16;" :: "r"(s), "l"(gptr));
}
#define CP_COMMIT() asm volatile("cp.async.commit_group;")
#define CP_WAIT1()  asm volatile("cp.async.wait_group 1;")
#define CP_WAIT0()  asm volatile("cp.async.wait_group 0;")

// ---------------------------------------------------------------------------
// Kernel 0: pre-convert the three W matrices to tf32 bits (once per launch).
// 3 * 16384 float4s; grid 192 x 256.
// ---------------------------------------------------------------------------
__global__ __launch_bounds__(256)
void wconv_kernel(const float* __restrict__ Wq,
                  const float* __restrict__ Wk,
                  const float* __restrict__ Wv)
{
    const int t = blockIdx.x * 256 + threadIdx.x;   // 0 .. 3*16384-1
    const int w = t >> 14;
    const int e = t & 16383;
    const float* W = (w == 0) ? Wq : (w == 1) ? Wk : Wv;
    float4 v = *(const float4*)&W[e * 4];
    uint4 u;
    u.x = f2tf(v.x); u.y = f2tf(v.y); u.z = f2tf(v.z); u.w = f2tf(v.w);
    *(uint4*)&g_Wt[w][e * 4] = u;
}

// ---------------------------------------------------------------------------
// Kernel 1: FUSED QKV projection, tf32 MMA + cp.async 2-stage pipeline.
// 256 thr / 8 warps; tile M=64 rows x (3 outputs x 64 cols), k-chunk 16.
// warp -> (mrow = (warp>>1)*16, nhalf = warp&1 -> cols nhalf*32..+31).
// X staged raw fp32 (cvt at a-frag read); W staged as tf32 bits (no cvt).
// Xs stride 20: a-frag banks 20g+c — all 32 distinct, conflict-free.
// Ws stride 72 (=8 mod 32): b-frag banks 8c+g — bijective, conflict-free.
// ---------------------------------------------------------------------------
__global__ __launch_bounds__(256, 2)
void proj_kernel(const float* __restrict__ x)
{
    __shared__ float    Xs[2][64][20];       // raw fp32, 64 rows x 16 k
    __shared__ unsigned Ws[2][3][16][72];    // tf32 bits, 16 k x 64 n, x3

    const int tid  = threadIdx.x;
    const int warp = tid >> 5;
    const int lane = tid & 31;
    const int g    = lane >> 2;   // 0..7
    const int c    = lane & 3;    // 0..3
    const int mrow = (warp >> 1) * 16;
    const int nh   = warp & 1;
    const int row0 = blockIdx.x * 64;

    // per-thread load indices: X 1 float4, W 1 float4 per matrix, per chunk
    const int xr = tid >> 2,  xs = tid & 3;
    const int wr = tid >> 4,  ws = tid & 15;

    float acc[3][4][4];
    #pragma unroll
    for (int w = 0; w < 3; w++)
        #pragma unroll
        for (int nt = 0; nt < 4; nt++)
            #pragma unroll
            for (int j = 0; j < 4; j++) acc[w][nt][j] = 0.0f;

    // ---- prologue: chunk 0 into stage 0 ----
    {
        cp16(&Xs[0][xr][xs * 4], &x[(size_t)(row0 + xr) * DIM + xs * 4]);
        #pragma unroll
        for (int w = 0; w < 3; w++)
            cp16(&Ws[0][w][wr][ws * 4], &g_Wt[w][(size_t)wr * HEAD + ws * 4]);
        CP_COMMIT();
    }

    #pragma unroll 1
    for (int ck = 0; ck < 64; ck++) {
        const int st = ck & 1;
        if (ck < 63) {
            const int k0 = (ck + 1) * 16;
            const int sn = st ^ 1;
            cp16(&Xs[sn][xr][xs * 4], &x[(size_t)(row0 + xr) * DIM + k0 + xs * 4]);
            #pragma unroll
            for (int w = 0; w < 3; w++)
                cp16(&Ws[sn][w][wr][ws * 4], &g_Wt[w][(size_t)(k0 + wr) * HEAD + ws * 4]);
            CP_COMMIT();
            CP_WAIT1();
        } else {
            CP_WAIT0();
        }
        __syncthreads();

        #pragma unroll
        for (int ks = 0; ks < 2; ks++) {
            unsigned a[4];
            a[0] = f2tf(Xs[st][mrow + g][ks * 8 + c]);
            a[1] = f2tf(Xs[st][mrow + g + 8][ks * 8 + c]);
            a[2] = f2tf(Xs[st][mrow + g][ks * 8 + c + 4]);
            a[3] = f2tf(Xs[st][mrow + g + 8][ks * 8 + c + 4]);
            #pragma unroll
            for (int w = 0; w < 3; w++) {
                #pragma unroll
                for (int nt = 0; nt < 4; nt++) {
                    const int ntg = nh * 4 + nt;
                    unsigned b[2];
                    b[0] = Ws[st][w][ks * 8 + c][ntg * 8 + g];
                    b[1] = Ws[st][w][ks * 8 + c + 4][ntg * 8 + g];
                    mma_tf32(acc[w][nt], a, b);
                }
            }
        }
        __syncthreads();
    }

    // epilogue: store all three projections
    #pragma unroll
    for (int w = 0; w < 3; w++) {
        float* out = (w == 0) ? g_Q : (w == 1) ? g_K : g_V;
        #pragma unroll
        for (int nt = 0; nt < 4; nt++) {
            const int ntg = nh * 4 + nt;
            float2 lo; lo.x = acc[w][nt][0]; lo.y = acc[w][nt][1];
            float2 hi; hi.x = acc[w][nt][2]; hi.y = acc[w][nt][3];
            *(float2*)&out[(size_t)(row0 + mrow + g)     * HEAD + ntg * 8 + 2 * c] = lo;
            *(float2*)&out[(size_t)(row0 + mrow + g + 8) * HEAD + ntg * 8 + 2 * c] = hi;
        }
    }
}

// ---------------------------------------------------------------------------
// Kernel 2: fused causal flash attention, tf32, split-K over 2 blocks.
// (unchanged from R8 — proven at 5.9e-4 / ~50us)
// ---------------------------------------------------------------------------
__global__ __launch_bounds__(128)
void attn_kernel()
{
    __shared__ unsigned Ks[64][68];   // K tf32 bits; P tf32 bits after scores
    __shared__ unsigned Vs[64][72];   // V tf32 bits

    const int tid  = threadIdx.x;
    const int warp = tid >> 5;
    const int lane = tid & 31;
    const int g    = lane >> 2;
    const int c    = lane & 3;

    const int qt   = (NQT2 - 1) - (blockIdx.x >> 1);   // heavy-first
    const int half = blockIdx.x & 1;
    const int b    = blockIdx.y;
    const size_t base = (size_t)b * SEQ * HEAD;
    const int qg0   = qt * BQ;
    const int qrow0 = qg0 + 16 * warp;

    const int nkt  = qt + 1;
    const int h    = (nkt + 1) >> 1;
    const int ktlo = half ? h : 0;
    const int kthi = half ? nkt : h;

    unsigned Qf[8][4];
    #pragma unroll
    for (int ks = 0; ks < 8; ks++) {
        Qf[ks][0] = f2tf(0.125f * g_Q[base + (size_t)(qrow0 + g)     * HEAD + ks * 8 + c]);
        Qf[ks][1] = f2tf(0.125f * g_Q[base + (size_t)(qrow0 + g + 8) * HEAD + ks * 8 + c]);
        Qf[ks][2] = f2tf(0.125f * g_Q[base + (size_t)(qrow0 + g)     * HEAD + ks * 8 + c + 4]);
        Qf[ks][3] = f2tf(0.125f * g_Q[base + (size_t)(qrow0 + g + 8) * HEAD + ks * 8 + c + 4]);
    }

    float O[8][4];
    #pragma unroll
    for (int nt = 0; nt < 8; nt++)
        #pragma unroll
        for (int j = 0; j < 4; j++) O[nt][j] = 0.0f;
    float mrun[2] = { NEG_BIG, NEG_BIG };
    float lrun[2] = { 0.0f, 0.0f };

    #pragma unroll 1
    for (int kt = ktlo; kt < kthi; kt++) {
        const int k0 = kt * TK;
        __syncthreads();   // sync_a

        #pragma unroll
        for (int it = 0; it < 8; it++) {
            const int idx = tid + it * 128;
            const int key = idx >> 4;
            const int d4  = idx & 15;
            float4 kv = *(const float4*)&g_K[base + (size_t)(k0 + key) * HEAD + d4 * 4];
            uint4 ku; ku.x = f2tf(kv.x); ku.y = f2tf(kv.y); ku.z = f2tf(kv.z); ku.w = f2tf(kv.w);
            *(uint4*)&Ks[key][d4 * 4] = ku;
            float4 vv = *(const float4*)&g_V[base + (size_t)(k0 + key) * HEAD + d4 * 4];
            uint4 vu; vu.x = f2tf(vv.x); vu.y = f2tf(vv.y); vu.z = f2tf(vv.z); vu.w = f2tf(vv.w);
            *(uint4*)&Vs[key][d4 * 4] = vu;
        }
        __syncthreads();   // sync_b

        float S[8][4];
        #pragma unroll
        for (int nt = 0; nt < 8; nt++)
            #pragma unroll
            for (int j = 0; j < 4; j++) S[nt][j] = 0.0f;

        #pragma unroll
        for (int ks = 0; ks < 8; ks++) {
            #pragma unroll
            for (int nt = 0; nt < 8; nt++) {
                unsigned bf[2];
                bf[0] = Ks[nt * 8 + g][ks * 8 + c];
                bf[1] = Ks[nt * 8 + g][ks * 8 + c + 4];
                mma_tf32(S[nt], Qf[ks], bf);
            }
        }

        if (kt == qt) {
            #pragma unroll
            for (int nt = 0; nt < 8; nt++)
                #pragma unroll
                for (int j = 0; j < 4; j++) {
                    const int col = k0 + nt * 8 + 2 * c + (j & 1);
                    const int row = qrow0 + g + ((j >= 2) ? 8 : 0);
                    if (col > row) S[nt][j] = NEG_BIG;
                }
        }

        float mx0 = NEG_BIG, mx1 = NEG_BIG;
        #pragma unroll
        for (int nt = 0; nt < 8; nt++) {
            mx0 = fmaxf(mx0, fmaxf(S[nt][0], S[nt][1]));
            mx1 = fmaxf(mx1, fmaxf(S[nt][2], S[nt][3]));
        }
        mx0 = fmaxf(mx0, __shfl_xor_sync(0xffffffffu, mx0, 1));
        mx0 = fmaxf(mx0, __shfl_xor_sync(0xffffffffu, mx0, 2));
        mx1 = fmaxf(mx1, __shfl_xor_sync(0xffffffffu, mx1, 1));
        mx1 = fmaxf(mx1, __shfl_xor_sync(0xffffffffu, mx1, 2));

        const float mn0 = fmaxf(mrun[0], mx0);
        const float mn1 = fmaxf(mrun[1], mx1);
        const float al0 = __expf(mrun[0] - mn0);
        const float al1 = __expf(mrun[1] - mn1);

        float ps0 = 0.0f, ps1 = 0.0f;
        #pragma unroll
        for (int nt = 0; nt < 8; nt++) {
            float p0 = __uint_as_float(f2tf(__expf(S[nt][0] - mn0)));
            float p1 = __uint_as_float(f2tf(__expf(S[nt][1] - mn0)));
            float p2 = __uint_as_float(f2tf(__expf(S[nt][2] - mn1)));
            float p3 = __uint_as_float(f2tf(__expf(S[nt][3] - mn1)));
            S[nt][0] = p0; S[nt][1] = p1; S[nt][2] = p2; S[nt][3] = p3;
            ps0 += p0 + p1;
            ps1 += p2 + p3;
        }
        ps0 += __shfl_xor_sync(0xffffffffu, ps0, 1);
        ps0 += __shfl_xor_sync(0xffffffffu, ps0, 2);
        ps1 += __shfl_xor_sync(0xffffffffu, ps1, 1);
        ps1 += __shfl_xor_sync(0xffffffffu, ps1, 2);

        lrun[0] = lrun[0] * al0 + ps0;
        lrun[1] = lrun[1] * al1 + ps1;
        mrun[0] = mn0;
        mrun[1] = mn1;
        #pragma unroll
        for (int nt = 0; nt < 8; nt++) {
            O[nt][0] *= al0; O[nt][1] *= al0;
            O[nt][2] *= al1; O[nt][3] *= al1;
        }

        __syncthreads();   // sync_c

        #pragma unroll
        for (int nt = 0; nt < 8; nt++) {
            uint2 lo; lo.x = __float_as_uint(S[nt][0]); lo.y = __float_as_uint(S[nt][1]);
            uint2 hi; hi.x = __float_as_uint(S[nt][2]); hi.y = __float_as_uint(S[nt][3]);
            *(uint2*)&Ks[16 * warp + g][nt * 8 + 2 * c]     = lo;
            *(uint2*)&Ks[16 * warp + g + 8][nt * 8 + 2 * c] = hi;
        }
        __syncwarp();

        #pragma unroll
        for (int kp = 0; kp < 8; kp++) {
            unsigned a[4];
            a[0] = Ks[16 * warp + g][kp * 8 + c];
            a[1] = Ks[16 * warp + g + 8][kp * 8 + c];
            a[2] = Ks[16 * warp + g][kp * 8 + c + 4];
            a[3] = Ks[16 * warp + g + 8][kp * 8 + c + 4];
            #pragma unroll
            for (int nt = 0; nt < 8; nt++) {
                unsigned bf[2];
                bf[0] = Vs[kp * 8 + c][nt * 8 + g];
                bf[1] = Vs[kp * 8 + c + 4][nt * 8 + g];
                mma_tf32(O[nt], a, bf);
            }
        }
    }

    float* Op = g_Op[half];
    #pragma unroll
    for (int nt = 0; nt < 8; nt++) {
        float2 lo; lo.x = O[nt][0]; lo.y = O[nt][1];
        float2 hi; hi.x = O[nt][2]; hi.y = O[nt][3];
        *(float2*)&Op[base + (size_t)(qrow0 + g)     * HEAD + nt * 8 + 2 * c] = lo;
        *(float2*)&Op[base + (size_t)(qrow0 + g + 8) * HEAD + nt * 8 + 2 * c] = hi;
    }
    if (c == 0) {
        const int rg = b * SEQ + qrow0 + g;
        g_m[half][rg]     = mrun[0];
        g_l[half][rg]     = lrun[0];
        g_m[half][rg + 8] = mrun[1];
        g_l[half][rg + 8] = lrun[1];
    }
}

// ---------------------------------------------------------------------------
// Kernel 3: split-K combine (unchanged from R8).
// ---------------------------------------------------------------------------
__global__ __launch_bounds__(128)
void combine_kernel(float* __restrict__ z)
{
    const int tid  = threadIdx.x;
    const int r    = blockIdx.x * 32 + (tid >> 2);
    const int part = tid & 3;

    const float m0 = g_m[0][r], m1 = g_m[1][r];
    const float l0 = g_l[0][r], l1 = g_l[1][r];
    const float M  = fmaxf(m0, m1);
    const float w0 = __expf(m0 - M);
    const float w1 = __expf(m1 - M);
    const float inv = 1.0f / (l0 * w0 + l1 * w1);

    const size_t rb = (size_t)r * HEAD + part * 16;
    #pragma unroll
    for (int d4 = 0; d4 < 4; d4++) {
        float4 a  = *(const float4*)&g_Op[0][rb + d4 * 4];
        float4 bq = *(const float4*)&g_Op[1][rb + d4 * 4];
        float4 o;
        o.x = (a.x * w0 + bq.x * w1) * inv;
        o.y = (a.y * w0 + bq.y * w1) * inv;
        o.z = (a.z * w0 + bq.z * w1) * inv;
        o.w = (a.w * w0 + bq.w * w1) * inv;
        *(float4*)&z[rb + d4 * 4] = o;
    }
}

// ---------------------------------------------------------------------------
extern "C" void kernel_launch(void* const* d_in, const int* in_sizes, int n_in,
                              void* d_out, int out_size)
{
    const float* x  = (const float*)d_in[0];
    const float* Wk = (const float*)d_in[1];
    const float* Wq = (const float*)d_in[2];
    const float* Wv = (const float*)d_in[3];
    float* z = (float*)d_out;
    (void)in_sizes; (void)n_in; (void)out_size;

    wconv_kernel<<<192, 256>>>(Wq, Wk, Wv);

    proj_kernel<<<MROWS / 64, 256>>>(x);

    dim3 agrid(2 * NQT2, BATCH);
    attn_kernel<<<agrid, 128>>>();

    combine_kernel<<<MROWS / 32, 128>>>(z);
}